// round 10
// baseline (speedup 1.0000x reference)
#include <cuda_runtime.h>
#include <cuda_bf16.h>
#include <math.h>
#include <stdint.h>

#define BATCH 8
#define CC 512
#define NN 4096
#define GG 32
#define CPG 16

// ---- scratch (static device globals; allowed by harness rules) ----
__device__ __nv_bfloat16 g_qt[(size_t)BATCH * NN * CC];    // q_t  [b][n][c]
__device__ __nv_bfloat16 g_ktb[(size_t)BATCH * NN * CC];   // k_t  [b][m][c]
__device__ __nv_bfloat16 g_kb[(size_t)BATCH * CC * NN];    // k    [b][c][m]
__device__ __nv_bfloat16 g_xt[(size_t)BATCH * NN * CC];    // x_t  [b][n][c]
__device__ __nv_bfloat16 g_attt[(size_t)BATCH * NN * CC];  // att_t[b][n][c]
__device__ __nv_bfloat16 g_s[(size_t)BATCH * NN * NN];     // scores/probs [b][n][m]
__device__ __nv_bfloat16 g_qwf[(size_t)BATCH * CC * CC];   // folded q weights
__device__ __nv_bfloat16 g_kwf[(size_t)BATCH * CC * CC];   // folded k weights
__device__ __nv_bfloat16 g_pwf[(size_t)CC * CC];           // proj weights bf16
__device__ float g_stats[BATCH * GG * 2];
__device__ float g_qbf[BATCH * CC];
__device__ float g_kbf[BATCH * CC];

// ============================================================
// helpers
// ============================================================
__device__ __forceinline__ unsigned packbf(float x, float y) {
    __nv_bfloat162 h = __float22bfloat162_rn(make_float2(x, y));
    return *reinterpret_cast<unsigned*>(&h);
}

__device__ __forceinline__ void mma16(float* c, unsigned a0, unsigned a1, unsigned a2, unsigned a3,
                                      unsigned b0, unsigned b1) {
    asm volatile(
        "mma.sync.aligned.m16n8k16.row.col.f32.bf16.bf16.f32 "
        "{%0,%1,%2,%3},{%4,%5,%6,%7},{%8,%9},{%0,%1,%2,%3};"
        : "+f"(c[0]), "+f"(c[1]), "+f"(c[2]), "+f"(c[3])
        : "r"(a0), "r"(a1), "r"(a2), "r"(a3), "r"(b0), "r"(b1));
}

#define LDSM4(r0, r1, r2, r3, addr) \
    asm volatile("ldmatrix.sync.aligned.m8n8.x4.shared.b16 {%0,%1,%2,%3}, [%4];" \
                 : "=r"(r0), "=r"(r1), "=r"(r2), "=r"(r3) : "r"(addr))

__device__ __forceinline__ void cp16(void* smem_dst, const void* gsrc) {
    unsigned s = (unsigned)__cvta_generic_to_shared(smem_dst);
    asm volatile("cp.async.cg.shared.global [%0], [%1], 16;" :: "r"(s), "l"(gsrc));
}
#define CP_COMMIT asm volatile("cp.async.commit_group;")
#define CP_WAIT1 asm volatile("cp.async.wait_group 1;")
#define CP_WAIT0 asm volatile("cp.async.wait_group 0;")

__device__ __forceinline__ uint32_t smem_u32(const void* p) {
    uint32_t a;
    asm("{ .reg .u64 t; cvta.to.shared.u64 t, %1; cvt.u32.u64 %0, t; }" : "=r"(a) : "l"(p));
    return a;
}

// ============================================================
// Unified bf16 GEMM mainloop, CTA tile 128x128, 4 warps (128 thr),
// warp tile 64x64 (2x2 layout), 3-stage cp.async, one sync per chunk.
//   acc[mi][ni][] += A[128 m][k] · B[128 n][k]^T  over K = NCH*64
// Operands MK-major bf16 (k contiguous), ld in elements.
// smem stage s at s*36864: A tile [128][72 bf16], B tile at +18432.
// ============================================================
#define STAGE_B 36864
#define SMEM_DYN (3 * STAGE_B)

__device__ __forceinline__ void bf_gemm(const __nv_bfloat16* A, size_t ldA,
                                        const __nv_bfloat16* B, size_t ldB,
                                        int NCH, char* sdyn, uint32_t sbase,
                                        float acc[4][8][4]) {
    int tid = threadIdx.x, lane = tid & 31, wid = tid >> 5;
    int wm = (wid & 1) * 64, wn = (wid >> 1) * 64;
    int lrow = tid >> 3, lseg = tid & 7;

    // ldmatrix lane-address offsets (bytes)
    uint32_t a_off = (uint32_t)(((lane & 7) + ((lane >> 3) & 1) * 8) * 144 + (lane >> 4) * 16);
    uint32_t b_off = (uint32_t)((((lane >> 4) << 3) + (lane & 7)) * 144 + ((lane >> 3) & 1) * 16);

#define BF_LOAD(st, c0)                                                                   \
    {                                                                                     \
        _Pragma("unroll") for (int r = 0; r < 8; r++) {                                   \
            int rr = lrow + r * 16;                                                       \
            cp16(sdyn + (st) * STAGE_B + rr * 144 + lseg * 16,                            \
                 A + (size_t)rr * ldA + (c0) + lseg * 8);                                 \
            cp16(sdyn + (st) * STAGE_B + 18432 + rr * 144 + lseg * 16,                    \
                 B + (size_t)rr * ldB + (c0) + lseg * 8);                                 \
        }                                                                                 \
    }

    BF_LOAD(0, 0);
    CP_COMMIT;
    BF_LOAD(1, 64);
    CP_COMMIT;
    int st = 0;
    for (int it = 0; it < NCH; it++) {
        if (it + 1 < NCH) { CP_WAIT1; } else { CP_WAIT0; }
        __syncthreads();
        if (it + 2 < NCH) {
            int ld = st + 2;
            if (ld >= 3) ld -= 3;
            BF_LOAD(ld, (it + 2) * 64);
            CP_COMMIT;
        }
        uint32_t sA = sbase + st * STAGE_B + wm * 144;
        uint32_t sB = sbase + st * STAGE_B + 18432 + wn * 144;
#pragma unroll
        for (int ks = 0; ks < 4; ks++) {
            unsigned a[4][4], bb[4][4];
#pragma unroll
            for (int mi = 0; mi < 4; mi++)
                LDSM4(a[mi][0], a[mi][1], a[mi][2], a[mi][3],
                      sA + mi * (16 * 144) + ks * 32 + a_off);
#pragma unroll
            for (int np = 0; np < 4; np++)
                LDSM4(bb[np][0], bb[np][1], bb[np][2], bb[np][3],
                      sB + np * (16 * 144) + ks * 32 + b_off);
#pragma unroll
            for (int mi = 0; mi < 4; mi++)
#pragma unroll
                for (int np = 0; np < 4; np++) {
                    mma16(acc[mi][np * 2], a[mi][0], a[mi][1], a[mi][2], a[mi][3],
                          bb[np][0], bb[np][1]);
                    mma16(acc[mi][np * 2 + 1], a[mi][0], a[mi][1], a[mi][2], a[mi][3],
                          bb[np][2], bb[np][3]);
                }
        }
        if (++st == 3) st = 0;
    }
    __syncthreads();  // protect smem reuse by epilogues
#undef BF_LOAD
}

// ============================================================
// Kernel 1: GroupNorm statistics
// ============================================================
__global__ void gn_stats_kernel(const float* __restrict__ x) {
    int b = blockIdx.x, g = blockIdx.y;
    const float* xp = x + ((size_t)(b * CC) + g * CPG) * NN;
    float s = 0.f, s2 = 0.f;
    for (int i = threadIdx.x; i < CPG * NN; i += 256) {
        float v = xp[i];
        s += v;
        s2 += v * v;
    }
    __shared__ float sh[256], sh2[256];
    sh[threadIdx.x] = s;
    sh2[threadIdx.x] = s2;
    __syncthreads();
    for (int off = 128; off > 0; off >>= 1) {
        if (threadIdx.x < off) {
            sh[threadIdx.x] += sh[threadIdx.x + off];
            sh2[threadIdx.x] += sh2[threadIdx.x + off];
        }
        __syncthreads();
    }
    if (threadIdx.x == 0) {
        const float inv = 1.f / (float)(CPG * NN);
        float mu = sh[0] * inv;
        float var = sh2[0] * inv - mu * mu;
        g_stats[(b * GG + g) * 2 + 0] = mu;
        g_stats[(b * GG + g) * 2 + 1] = rsqrtf(var + 1e-6f);
    }
}

// ============================================================
// Kernel 2: fold GN + softmax scale into bf16 weights + fp32 biases
// ============================================================
__global__ void fold_kernel(const float* __restrict__ qw, const float* __restrict__ qb,
                            const float* __restrict__ kw, const float* __restrict__ kb,
                            const float* __restrict__ pw,
                            const float* __restrict__ gamma, const float* __restrict__ beta) {
    int b = blockIdx.x, o0 = blockIdx.y * 128;
    __shared__ float ga[CC], be[CC];
    for (int c = threadIdx.x; c < CC; c += 256) {
        int g = c >> 4;
        float mu = g_stats[(b * GG + g) * 2 + 0];
        float rstd = g_stats[(b * GG + g) * 2 + 1];
        float gg = gamma[c] * rstd;
        ga[c] = gg;
        be[c] = beta[c] - mu * gg;
    }
    __syncthreads();
    const float s = rsqrtf((float)CC);
    for (int idx = threadIdx.x; idx < 128 * CC; idx += 256) {
        int o = o0 + (idx >> 9), c = idx & (CC - 1);
        g_qwf[((size_t)b * CC + o) * CC + c] = __float2bfloat16_rn(qw[(size_t)o * CC + c] * ga[c] * s);
        g_kwf[((size_t)b * CC + o) * CC + c] = __float2bfloat16_rn(kw[(size_t)o * CC + c] * ga[c]);
    }
    {
        int o = o0 + (threadIdx.x >> 1);
        int h = (threadIdx.x & 1) * 256;
        float sq = 0.f, sk = 0.f;
        for (int c = h; c < h + 256; c++) {
            sq += qw[(size_t)o * CC + c] * be[c];
            sk += kw[(size_t)o * CC + c] * be[c];
        }
        sq += __shfl_xor_sync(0xffffffffu, sq, 1);
        sk += __shfl_xor_sync(0xffffffffu, sk, 1);
        if ((threadIdx.x & 1) == 0) {
            g_qbf[b * CC + o] = (qb[o] + sq) * s;
            g_kbf[b * CC + o] = kb[o] + sk;
        }
    }
    if (b == 0) {
        for (int idx = threadIdx.x; idx < 128 * CC; idx += 256) {
            int o = o0 + (idx >> 9), c = idx & (CC - 1);
            g_pwf[(size_t)o * CC + c] = __float2bfloat16_rn(pw[(size_t)o * CC + c]);
        }
    }
}

// ============================================================
// Kernel 3: x[c][n] fp32 -> x_t[n][c] bf16 (tiled transpose)
// ============================================================
__global__ void xt_kernel(const float* __restrict__ x) {
    __shared__ float ts[32][33];
    int b = blockIdx.z;
    int n0 = blockIdx.x * 32, c0 = blockIdx.y * 32;
    int tx = threadIdx.x, ty = threadIdx.y;
#pragma unroll
    for (int r = 0; r < 4; r++) {
        int c = c0 + ty + r * 8;
        ts[tx][ty + r * 8] = x[((size_t)b * CC + c) * NN + n0 + tx];
    }
    __syncthreads();
#pragma unroll
    for (int r = 0; r < 4; r++) {
        int n = n0 + ty + r * 8;
        g_xt[((size_t)b * NN + n) * CC + c0 + tx] = __float2bfloat16_rn(ts[ty + r * 8][tx]);
    }
}

// ============================================================
// Kernel 4: q/k projection + transposed epilogues.
//   D[o 128][n 128] = W'[o][c] · x_t[n][c]^T
//   which=0 -> q_t[n][c];  which=1 -> k[c][m] AND k_t[m][c]
// ============================================================
__global__ __launch_bounds__(128, 2) void qk_bf_kernel() {
    extern __shared__ char sdyn[];
    uint32_t sbase = smem_u32(sdyn);
    int b = blockIdx.z >> 1, which = blockIdx.z & 1;
    int o_blk = blockIdx.y * 128, n_blk = blockIdx.x * 128;
    const __nv_bfloat16* A = (which ? g_kwf : g_qwf) + (size_t)b * CC * CC + (size_t)o_blk * CC;
    const __nv_bfloat16* B = g_xt + (size_t)b * NN * CC + (size_t)n_blk * CC;
    const float* bias = (which ? g_kbf : g_qbf) + b * CC;

    float acc[4][8][4] = {};
    bf_gemm(A, CC, B, CC, CC / 64, sdyn, sbase, acc);

    int tid = threadIdx.x, lane = tid & 31, wid = tid >> 5;
    int gid = lane >> 2, tig = lane & 3;
    int wm = (wid & 1) * 64, wn = (wid >> 1) * 64;

    __nv_bfloat16* T = (__nv_bfloat16*)sdyn;  // [128 n][136 o-pitch]
#pragma unroll
    for (int mi = 0; mi < 4; mi++) {
        int ol = wm + mi * 16 + gid;
        float bv0 = bias[o_blk + ol], bv1 = bias[o_blk + ol + 8];
#pragma unroll
        for (int ni = 0; ni < 8; ni++) {
            int nl = wn + ni * 8 + tig * 2;
            __nv_bfloat16 b00 = __float2bfloat16_rn(acc[mi][ni][0] + bv0);
            __nv_bfloat16 b01 = __float2bfloat16_rn(acc[mi][ni][1] + bv0);
            __nv_bfloat16 b10 = __float2bfloat16_rn(acc[mi][ni][2] + bv1);
            __nv_bfloat16 b11 = __float2bfloat16_rn(acc[mi][ni][3] + bv1);
            if (which) {
                __nv_bfloat162 p0; p0.x = b00; p0.y = b01;
                __nv_bfloat162 p1; p1.x = b10; p1.y = b11;
                *(__nv_bfloat162*)&g_kb[((size_t)b * CC + o_blk + ol) * NN + n_blk + nl] = p0;
                *(__nv_bfloat162*)&g_kb[((size_t)b * CC + o_blk + ol + 8) * NN + n_blk + nl] = p1;
            }
            T[nl * 136 + ol] = b00;
            T[(nl + 1) * 136 + ol] = b01;
            T[nl * 136 + ol + 8] = b10;
            T[(nl + 1) * 136 + ol + 8] = b11;
        }
    }
    __syncthreads();
    {
        __nv_bfloat16* dst = (which ? g_ktb : g_qt) + (size_t)b * NN * CC;
        int nl = tid;  // 128 rows, one per thread
        __nv_bfloat16* drow = dst + (size_t)(n_blk + nl) * CC + o_blk;
        const __nv_bfloat16* srow = T + nl * 136;
#pragma unroll
        for (int j = 0; j < 16; j++)
            *(uint4*)(drow + j * 8) = *(const uint4*)(srow + j * 8);
    }
}

// ============================================================
// Kernel 5: scores. S[n][m] = q_t[n][c] · k_t[m][c]^T  (bf16 out)
// ============================================================
__global__ __launch_bounds__(128, 2) void scores_bf_kernel() {
    extern __shared__ char sdyn[];
    uint32_t sbase = smem_u32(sdyn);
    int b = blockIdx.z;
    int nB = blockIdx.y * 128, mB = blockIdx.x * 128;
    const __nv_bfloat16* A = g_qt + (size_t)b * NN * CC + (size_t)nB * CC;
    const __nv_bfloat16* B = g_ktb + (size_t)b * NN * CC + (size_t)mB * CC;

    float acc[4][8][4] = {};
    bf_gemm(A, CC, B, CC, CC / 64, sdyn, sbase, acc);

    int tid = threadIdx.x, lane = tid & 31, wid = tid >> 5;
    int gid = lane >> 2, tig = lane & 3;
    int wm = (wid & 1) * 64, wn = (wid >> 1) * 64;
#pragma unroll
    for (int mi = 0; mi < 4; mi++) {
        int qrow = nB + wm + mi * 16 + gid;
        __nv_bfloat16* p0 = g_s + ((size_t)b * NN + qrow) * NN + mB;
        __nv_bfloat16* p1 = p0 + (size_t)8 * NN;
#pragma unroll
        for (int ni = 0; ni < 8; ni++) {
            int cb = wn + ni * 8 + tig * 2;
            *(unsigned*)(p0 + cb) = packbf(acc[mi][ni][0], acc[mi][ni][1]);
            *(unsigned*)(p1 + cb) = packbf(acc[mi][ni][2], acc[mi][ni][3]);
        }
    }
}

// ============================================================
// Kernel 6: row softmax over m, bf16 in/out, fp32 math, uint4 I/O.
// ============================================================
__global__ void softmax_kernel() {
    int b = blockIdx.y;
    int row = blockIdx.x;
    uint4* p = (uint4*)(g_s + ((size_t)b * NN + row) * NN);  // 512 uint4
    int tid = threadIdx.x;

    uint4 u0 = p[tid];
    uint4 u1 = p[tid + 256];
    float vals[16];
    float mx = -1e30f;
    {
        const unsigned us[8] = {u0.x, u0.y, u0.z, u0.w, u1.x, u1.y, u1.z, u1.w};
#pragma unroll
        for (int i = 0; i < 8; i++) {
            __nv_bfloat162 h = *reinterpret_cast<const __nv_bfloat162*>(&us[i]);
            float2 f = __bfloat1622float2(h);
            vals[2 * i] = f.x;
            vals[2 * i + 1] = f.y;
            mx = fmaxf(mx, fmaxf(f.x, f.y));
        }
    }
    __shared__ float sred[64];
#pragma unroll
    for (int off = 16; off > 0; off >>= 1)
        mx = fmaxf(mx, __shfl_xor_sync(0xffffffffu, mx, off));
    if ((tid & 31) == 0) sred[tid >> 5] = mx;
    __syncthreads();
    if (tid < 32) {
        float v = (tid < 8) ? sred[tid] : -1e30f;
#pragma unroll
        for (int off = 4; off > 0; off >>= 1)
            v = fmaxf(v, __shfl_xor_sync(0xffffffffu, v, off));
        if (tid == 0) sred[32] = v;
    }
    __syncthreads();
    mx = sred[32];

    float sum = 0.f;
#pragma unroll
    for (int i = 0; i < 16; i++) {
        vals[i] = __expf(vals[i] - mx);
        sum += vals[i];
    }
#pragma unroll
    for (int off = 16; off > 0; off >>= 1)
        sum += __shfl_xor_sync(0xffffffffu, sum, off);
    if ((tid & 31) == 0) sred[tid >> 5] = sum;
    __syncthreads();
    if (tid < 32) {
        float v = (tid < 8) ? sred[tid] : 0.f;
#pragma unroll
        for (int off = 4; off > 0; off >>= 1)
            v += __shfl_xor_sync(0xffffffffu, v, off);
        if (tid == 0) sred[33] = v;
    }
    __syncthreads();
    float inv = 1.f / sred[33];
    uint4 o0, o1;
    o0.x = packbf(vals[0] * inv, vals[1] * inv);
    o0.y = packbf(vals[2] * inv, vals[3] * inv);
    o0.z = packbf(vals[4] * inv, vals[5] * inv);
    o0.w = packbf(vals[6] * inv, vals[7] * inv);
    o1.x = packbf(vals[8] * inv, vals[9] * inv);
    o1.y = packbf(vals[10] * inv, vals[11] * inv);
    o1.z = packbf(vals[12] * inv, vals[13] * inv);
    o1.w = packbf(vals[14] * inv, vals[15] * inv);
    p[tid] = o0;
    p[tid + 256] = o1;
}

// ============================================================
// Kernel 7: AV. D[c 128][n 128] = k[c][m] · P[n][m]^T -> att_t[n][c] bf16
// ============================================================
__global__ __launch_bounds__(128, 2) void av_bf_kernel() {
    extern __shared__ char sdyn[];
    uint32_t sbase = smem_u32(sdyn);
    int b = blockIdx.z;
    int cB = blockIdx.y * 128, nB = blockIdx.x * 128;
    const __nv_bfloat16* A = g_kb + (size_t)b * CC * NN + (size_t)cB * NN;
    const __nv_bfloat16* B = g_s + (size_t)b * NN * NN + (size_t)nB * NN;

    float acc[4][8][4] = {};
    bf_gemm(A, NN, B, NN, NN / 64, sdyn, sbase, acc);

    int tid = threadIdx.x, lane = tid & 31, wid = tid >> 5;
    int gid = lane >> 2, tig = lane & 3;
    int wm = (wid & 1) * 64, wn = (wid >> 1) * 64;

    __nv_bfloat16* T = (__nv_bfloat16*)sdyn;  // [128 n][136 c-pitch]
#pragma unroll
    for (int mi = 0; mi < 4; mi++) {
        int cl = wm + mi * 16 + gid;
#pragma unroll
        for (int ni = 0; ni < 8; ni++) {
            int nl = wn + ni * 8 + tig * 2;
            T[nl * 136 + cl] = __float2bfloat16_rn(acc[mi][ni][0]);
            T[(nl + 1) * 136 + cl] = __float2bfloat16_rn(acc[mi][ni][1]);
            T[nl * 136 + cl + 8] = __float2bfloat16_rn(acc[mi][ni][2]);
            T[(nl + 1) * 136 + cl + 8] = __float2bfloat16_rn(acc[mi][ni][3]);
        }
    }
    __syncthreads();
    {
        int nl = tid;  // 128 rows, one per thread
        __nv_bfloat16* drow = g_attt + ((size_t)b * NN + nB + nl) * CC + cB;
        const __nv_bfloat16* srow = T + nl * 136;
#pragma unroll
        for (int j = 0; j < 16; j++)
            *(uint4*)(drow + j * 8) = *(const uint4*)(srow + j * 8);
    }
}

// ============================================================
// Kernel 8: proj + bias + residual.
//   out[o][n] = x[o][n] + pb[o] + pw[o][c] · att_t[n][c]^T
// ============================================================
__global__ __launch_bounds__(128, 2) void proj_bf_kernel(const float* __restrict__ x,
                                                         const float* __restrict__ pb,
                                                         float* __restrict__ out) {
    extern __shared__ char sdyn[];
    uint32_t sbase = smem_u32(sdyn);
    int b = blockIdx.z;
    int o_blk = blockIdx.y * 128, n_blk = blockIdx.x * 128;
    const __nv_bfloat16* A = g_pwf + (size_t)o_blk * CC;
    const __nv_bfloat16* B = g_attt + (size_t)b * NN * CC + (size_t)n_blk * CC;

    float acc[4][8][4] = {};
    bf_gemm(A, CC, B, CC, CC / 64, sdyn, sbase, acc);

    int tid = threadIdx.x, lane = tid & 31, wid = tid >> 5;
    int gid = lane >> 2, tig = lane & 3;
    int wm = (wid & 1) * 64, wn = (wid >> 1) * 64;
#pragma unroll
    for (int mi = 0; mi < 4; mi++) {
        int o = o_blk + wm + mi * 16 + gid;
        float bv0 = pb[o], bv1 = pb[o + 8];
        size_t base0 = ((size_t)b * CC + o) * NN + n_blk;
        size_t base1 = base0 + (size_t)8 * NN;
#pragma unroll
        for (int ni = 0; ni < 8; ni++) {
            int cb = wn + ni * 8 + tig * 2;
            float2 x0 = *(const float2*)(x + base0 + cb);
            float2 x1 = *(const float2*)(x + base1 + cb);
            *(float2*)(out + base0 + cb) =
                make_float2(acc[mi][ni][0] + bv0 + x0.x, acc[mi][ni][1] + bv0 + x0.y);
            *(float2*)(out + base1 + cb) =
                make_float2(acc[mi][ni][2] + bv1 + x1.x, acc[mi][ni][3] + bv1 + x1.y);
        }
    }
}

// ============================================================
// launch
// ============================================================
extern "C" void kernel_launch(void* const* d_in, const int* in_sizes, int n_in,
                              void* d_out, int out_size) {
    const float* x     = (const float*)d_in[0];
    const float* gamma = (const float*)d_in[1];
    const float* beta  = (const float*)d_in[2];
    const float* q_w   = (const float*)d_in[3];
    const float* q_b   = (const float*)d_in[4];
    const float* k_w   = (const float*)d_in[5];
    const float* k_b   = (const float*)d_in[6];
    const float* p_w   = (const float*)d_in[7];
    const float* p_b   = (const float*)d_in[8];
    float* out = (float*)d_out;

    (void)in_sizes; (void)n_in; (void)out_size;

    cudaFuncSetAttribute(qk_bf_kernel, cudaFuncAttributeMaxDynamicSharedMemorySize, SMEM_DYN);
    cudaFuncSetAttribute(scores_bf_kernel, cudaFuncAttributeMaxDynamicSharedMemorySize, SMEM_DYN);
    cudaFuncSetAttribute(av_bf_kernel, cudaFuncAttributeMaxDynamicSharedMemorySize, SMEM_DYN);
    cudaFuncSetAttribute(proj_bf_kernel, cudaFuncAttributeMaxDynamicSharedMemorySize, SMEM_DYN);

    gn_stats_kernel<<<dim3(BATCH, GG), 256>>>(x);
    fold_kernel<<<dim3(BATCH, 4), 256>>>(q_w, q_b, k_w, k_b, p_w, gamma, beta);
    xt_kernel<<<dim3(NN / 32, CC / 32, BATCH), dim3(32, 8)>>>(x);

    qk_bf_kernel<<<dim3(NN / 128, CC / 128, BATCH * 2), 128, SMEM_DYN>>>();
    scores_bf_kernel<<<dim3(NN / 128, NN / 128, BATCH), 128, SMEM_DYN>>>();
    softmax_kernel<<<dim3(NN, BATCH), 256>>>();
    av_bf_kernel<<<dim3(NN / 128, CC / 128, BATCH), 128, SMEM_DYN>>>();
    proj_bf_kernel<<<dim3(NN / 128, CC / 128, BATCH), 128, SMEM_DYN>>>(x, p_b, out);
}

// round 11
// speedup vs baseline: 1.0322x; 1.0322x over previous
#include <cuda_runtime.h>
#include <cuda_bf16.h>
#include <cuda_fp8.h>
#include <math.h>
#include <stdint.h>

#define BATCH 8
#define CC 512
#define NN 4096
#define GG 32
#define CPG 16

#define QSCALE 32.0f
#define QINV   0.03125f
#define PSCALE 1024.0f
#define PINV   0.0009765625f

// ---- scratch (static device globals; allowed by harness rules) ----
__device__ unsigned char g_q8[(size_t)BATCH * NN * CC];    // q_t  [b][n][c] e4m3 (x32)
__device__ unsigned char g_k8t[(size_t)BATCH * NN * CC];   // k_t  [b][m][c] e4m3
__device__ unsigned char g_kv8[(size_t)BATCH * CC * NN];   // k(v) [b][c][m] e4m3
__device__ __nv_bfloat16 g_xt[(size_t)BATCH * NN * CC];    // x_t  [b][n][c] bf16
__device__ __nv_bfloat16 g_attt[(size_t)BATCH * NN * CC];  // att_t[b][n][c] bf16
__device__ __nv_bfloat16 g_s[(size_t)BATCH * NN * NN];     // scores bf16 (S' = 32*S)
__device__ unsigned char g_p[(size_t)BATCH * NN * NN];     // probs e4m3 (P' = 1024*P)
__device__ __nv_bfloat16 g_qwf[(size_t)BATCH * CC * CC];
__device__ __nv_bfloat16 g_kwf[(size_t)BATCH * CC * CC];
__device__ __nv_bfloat16 g_pwf[(size_t)CC * CC];
__device__ float g_stats[BATCH * GG * 2];
__device__ float g_qbf[BATCH * CC];
__device__ float g_kbf[BATCH * CC];

// ============================================================
// helpers
// ============================================================
__device__ __forceinline__ unsigned packbf(float x, float y) {
    __nv_bfloat162 h = __float22bfloat162_rn(make_float2(x, y));
    return *reinterpret_cast<unsigned*>(&h);
}

__device__ __forceinline__ unsigned short pack2e4(float lo, float hi) {
    unsigned short r;
    asm("cvt.rn.satfinite.e4m3x2.f32 %0, %1, %2;" : "=h"(r) : "f"(hi), "f"(lo));
    return r;  // low byte = lo, high byte = hi
}
__device__ __forceinline__ unsigned char f8(float v) {
    return (unsigned char)(pack2e4(v, v) & 0xFF);
}

__device__ __forceinline__ void mma16(float* c, unsigned a0, unsigned a1, unsigned a2, unsigned a3,
                                      unsigned b0, unsigned b1) {
    asm volatile(
        "mma.sync.aligned.m16n8k16.row.col.f32.bf16.bf16.f32 "
        "{%0,%1,%2,%3},{%4,%5,%6,%7},{%8,%9},{%0,%1,%2,%3};"
        : "+f"(c[0]), "+f"(c[1]), "+f"(c[2]), "+f"(c[3])
        : "r"(a0), "r"(a1), "r"(a2), "r"(a3), "r"(b0), "r"(b1));
}

__device__ __forceinline__ void mma32f8(float* c, unsigned a0, unsigned a1, unsigned a2, unsigned a3,
                                        unsigned b0, unsigned b1) {
    asm volatile(
        "mma.sync.aligned.m16n8k32.row.col.f32.e4m3.e4m3.f32 "
        "{%0,%1,%2,%3},{%4,%5,%6,%7},{%8,%9},{%0,%1,%2,%3};"
        : "+f"(c[0]), "+f"(c[1]), "+f"(c[2]), "+f"(c[3])
        : "r"(a0), "r"(a1), "r"(a2), "r"(a3), "r"(b0), "r"(b1));
}

#define LDSM4(r0, r1, r2, r3, addr) \
    asm volatile("ldmatrix.sync.aligned.m8n8.x4.shared.b16 {%0,%1,%2,%3}, [%4];" \
                 : "=r"(r0), "=r"(r1), "=r"(r2), "=r"(r3) : "r"(addr))

__device__ __forceinline__ void cp16(void* smem_dst, const void* gsrc) {
    unsigned s = (unsigned)__cvta_generic_to_shared(smem_dst);
    asm volatile("cp.async.cg.shared.global [%0], [%1], 16;" :: "r"(s), "l"(gsrc));
}
#define CP_COMMIT asm volatile("cp.async.commit_group;")
#define CP_WAIT1 asm volatile("cp.async.wait_group 1;")
#define CP_WAIT0 asm volatile("cp.async.wait_group 0;")

__device__ __forceinline__ uint32_t smem_u32(const void* p) {
    uint32_t a;
    asm("{ .reg .u64 t; cvta.to.shared.u64 t, %1; cvt.u32.u64 %0, t; }" : "=r"(a) : "l"(p));
    return a;
}

// ============================================================
// bf16 GEMM mainloop (R6 config: 128x128 tile, 8 warps 64x32, 2-stage).
// smem stage s at s*36864: A [128][72 bf16] (144 B pitch), B at +18432.
// ============================================================
#define STAGE_B 36864
#define SMEM_DYN (2 * STAGE_B)

__device__ __forceinline__ void bf_gemm(const __nv_bfloat16* A, size_t ldA,
                                        const __nv_bfloat16* B, size_t ldB,
                                        int NCH, char* sdyn, uint32_t sbase,
                                        float acc[4][4][4]) {
    int tid = threadIdx.x, lane = tid & 31, wid = tid >> 5;
    int wm = (wid & 1) * 64, wn = (wid >> 1) * 32;
    int lrow = tid >> 3, lseg = tid & 7;

    uint32_t a_off = (uint32_t)(((lane & 7) + ((lane >> 3) & 1) * 8) * 144 + (lane >> 4) * 16);
    uint32_t b_off = (uint32_t)((((lane >> 4) << 3) + (lane & 7)) * 144 + ((lane >> 3) & 1) * 16);

#define BF_LOAD(st, c0)                                                                   \
    {                                                                                     \
        _Pragma("unroll") for (int r = 0; r < 4; r++) {                                   \
            int rr = lrow + r * 32;                                                       \
            cp16(sdyn + (st) * STAGE_B + rr * 144 + lseg * 16,                            \
                 A + (size_t)rr * ldA + (c0) + lseg * 8);                                 \
            cp16(sdyn + (st) * STAGE_B + 18432 + rr * 144 + lseg * 16,                    \
                 B + (size_t)rr * ldB + (c0) + lseg * 8);                                 \
        }                                                                                 \
    }

    BF_LOAD(0, 0);
    CP_COMMIT;
    for (int it = 0; it < NCH; it++) {
        if (it + 1 < NCH) {
            BF_LOAD((it + 1) & 1, (it + 1) * 64);
            CP_COMMIT;
            CP_WAIT1;
        } else {
            CP_WAIT0;
        }
        __syncthreads();
        uint32_t sA = sbase + (it & 1) * STAGE_B + wm * 144;
        uint32_t sB = sbase + (it & 1) * STAGE_B + 18432 + wn * 144;
#pragma unroll
        for (int ks = 0; ks < 4; ks++) {
            unsigned a[4][4], bb[2][4];
#pragma unroll
            for (int mi = 0; mi < 4; mi++)
                LDSM4(a[mi][0], a[mi][1], a[mi][2], a[mi][3],
                      sA + mi * (16 * 144) + ks * 32 + a_off);
#pragma unroll
            for (int np = 0; np < 2; np++)
                LDSM4(bb[np][0], bb[np][1], bb[np][2], bb[np][3],
                      sB + np * (16 * 144) + ks * 32 + b_off);
#pragma unroll
            for (int mi = 0; mi < 4; mi++) {
                mma16(acc[mi][0], a[mi][0], a[mi][1], a[mi][2], a[mi][3], bb[0][0], bb[0][1]);
                mma16(acc[mi][1], a[mi][0], a[mi][1], a[mi][2], a[mi][3], bb[0][2], bb[0][3]);
                mma16(acc[mi][2], a[mi][0], a[mi][1], a[mi][2], a[mi][3], bb[1][0], bb[1][1]);
                mma16(acc[mi][3], a[mi][0], a[mi][1], a[mi][2], a[mi][3], bb[1][2], bb[1][3]);
            }
        }
        __syncthreads();
    }
#undef BF_LOAD
}

// ============================================================
// fp8 e4m3 GEMM mainloop — same skeleton, K-chunk = 128 fp8 (128 B rows).
// Fragment map of m16n8k32 e4m3 == m16n8k16 bf16 with byte-pairs as b16,
// so ldmatrix addressing is IDENTICAL (144 B pitch, ks*32 B = k32).
// ============================================================
__device__ __forceinline__ void f8_gemm(const unsigned char* A, size_t ldA,
                                        const unsigned char* B, size_t ldB,
                                        int NCH, char* sdyn, uint32_t sbase,
                                        float acc[4][4][4]) {
    int tid = threadIdx.x, lane = tid & 31, wid = tid >> 5;
    int wm = (wid & 1) * 64, wn = (wid >> 1) * 32;
    int lrow = tid >> 3, lseg = tid & 7;

    uint32_t a_off = (uint32_t)(((lane & 7) + ((lane >> 3) & 1) * 8) * 144 + (lane >> 4) * 16);
    uint32_t b_off = (uint32_t)((((lane >> 4) << 3) + (lane & 7)) * 144 + ((lane >> 3) & 1) * 16);

#define F8_LOAD(st, c0)                                                                   \
    {                                                                                     \
        _Pragma("unroll") for (int r = 0; r < 4; r++) {                                   \
            int rr = lrow + r * 32;                                                       \
            cp16(sdyn + (st) * STAGE_B + rr * 144 + lseg * 16,                            \
                 A + (size_t)rr * ldA + (c0) + lseg * 16);                                \
            cp16(sdyn + (st) * STAGE_B + 18432 + rr * 144 + lseg * 16,                    \
                 B + (size_t)rr * ldB + (c0) + lseg * 16);                                \
        }                                                                                 \
    }

    F8_LOAD(0, 0);
    CP_COMMIT;
    for (int it = 0; it < NCH; it++) {
        if (it + 1 < NCH) {
            F8_LOAD((it + 1) & 1, (it + 1) * 128);
            CP_COMMIT;
            CP_WAIT1;
        } else {
            CP_WAIT0;
        }
        __syncthreads();
        uint32_t sA = sbase + (it & 1) * STAGE_B + wm * 144;
        uint32_t sB = sbase + (it & 1) * STAGE_B + 18432 + wn * 144;
#pragma unroll
        for (int ks = 0; ks < 4; ks++) {
            unsigned a[4][4], bb[2][4];
#pragma unroll
            for (int mi = 0; mi < 4; mi++)
                LDSM4(a[mi][0], a[mi][1], a[mi][2], a[mi][3],
                      sA + mi * (16 * 144) + ks * 32 + a_off);
#pragma unroll
            for (int np = 0; np < 2; np++)
                LDSM4(bb[np][0], bb[np][1], bb[np][2], bb[np][3],
                      sB + np * (16 * 144) + ks * 32 + b_off);
#pragma unroll
            for (int mi = 0; mi < 4; mi++) {
                mma32f8(acc[mi][0], a[mi][0], a[mi][1], a[mi][2], a[mi][3], bb[0][0], bb[0][1]);
                mma32f8(acc[mi][1], a[mi][0], a[mi][1], a[mi][2], a[mi][3], bb[0][2], bb[0][3]);
                mma32f8(acc[mi][2], a[mi][0], a[mi][1], a[mi][2], a[mi][3], bb[1][0], bb[1][1]);
                mma32f8(acc[mi][3], a[mi][0], a[mi][1], a[mi][2], a[mi][3], bb[1][2], bb[1][3]);
            }
        }
        __syncthreads();
    }
#undef F8_LOAD
}

// ============================================================
// Kernel 1: GroupNorm statistics
// ============================================================
__global__ void gn_stats_kernel(const float* __restrict__ x) {
    int b = blockIdx.x, g = blockIdx.y;
    const float* xp = x + ((size_t)(b * CC) + g * CPG) * NN;
    float s = 0.f, s2 = 0.f;
    for (int i = threadIdx.x; i < CPG * NN; i += 256) {
        float v = xp[i];
        s += v;
        s2 += v * v;
    }
    __shared__ float sh[256], sh2[256];
    sh[threadIdx.x] = s;
    sh2[threadIdx.x] = s2;
    __syncthreads();
    for (int off = 128; off > 0; off >>= 1) {
        if (threadIdx.x < off) {
            sh[threadIdx.x] += sh[threadIdx.x + off];
            sh2[threadIdx.x] += sh2[threadIdx.x + off];
        }
        __syncthreads();
    }
    if (threadIdx.x == 0) {
        const float inv = 1.f / (float)(CPG * NN);
        float mu = sh[0] * inv;
        float var = sh2[0] * inv - mu * mu;
        g_stats[(b * GG + g) * 2 + 0] = mu;
        g_stats[(b * GG + g) * 2 + 1] = rsqrtf(var + 1e-6f);
    }
}

// ============================================================
// Kernel 2: fold GN + softmax scale into bf16 weights + fp32 biases
// ============================================================
__global__ void fold_kernel(const float* __restrict__ qw, const float* __restrict__ qb,
                            const float* __restrict__ kw, const float* __restrict__ kb,
                            const float* __restrict__ pw,
                            const float* __restrict__ gamma, const float* __restrict__ beta) {
    int b = blockIdx.x, o0 = blockIdx.y * 128;
    __shared__ float ga[CC], be[CC];
    for (int c = threadIdx.x; c < CC; c += 256) {
        int g = c >> 4;
        float mu = g_stats[(b * GG + g) * 2 + 0];
        float rstd = g_stats[(b * GG + g) * 2 + 1];
        float gg = gamma[c] * rstd;
        ga[c] = gg;
        be[c] = beta[c] - mu * gg;
    }
    __syncthreads();
    const float s = rsqrtf((float)CC);
    for (int idx = threadIdx.x; idx < 128 * CC; idx += 256) {
        int o = o0 + (idx >> 9), c = idx & (CC - 1);
        g_qwf[((size_t)b * CC + o) * CC + c] = __float2bfloat16_rn(qw[(size_t)o * CC + c] * ga[c] * s);
        g_kwf[((size_t)b * CC + o) * CC + c] = __float2bfloat16_rn(kw[(size_t)o * CC + c] * ga[c]);
    }
    {
        int o = o0 + (threadIdx.x >> 1);
        int h = (threadIdx.x & 1) * 256;
        float sq = 0.f, sk = 0.f;
        for (int c = h; c < h + 256; c++) {
            sq += qw[(size_t)o * CC + c] * be[c];
            sk += kw[(size_t)o * CC + c] * be[c];
        }
        sq += __shfl_xor_sync(0xffffffffu, sq, 1);
        sk += __shfl_xor_sync(0xffffffffu, sk, 1);
        if ((threadIdx.x & 1) == 0) {
            g_qbf[b * CC + o] = (qb[o] + sq) * s;
            g_kbf[b * CC + o] = kb[o] + sk;
        }
    }
    if (b == 0) {
        for (int idx = threadIdx.x; idx < 128 * CC; idx += 256) {
            int o = o0 + (idx >> 9), c = idx & (CC - 1);
            g_pwf[(size_t)o * CC + c] = __float2bfloat16_rn(pw[(size_t)o * CC + c]);
        }
    }
}

// ============================================================
// Kernel 3: x[c][n] fp32 -> x_t[n][c] bf16 (tiled transpose)
// ============================================================
__global__ void xt_kernel(const float* __restrict__ x) {
    __shared__ float ts[32][33];
    int b = blockIdx.z;
    int n0 = blockIdx.x * 32, c0 = blockIdx.y * 32;
    int tx = threadIdx.x, ty = threadIdx.y;
#pragma unroll
    for (int r = 0; r < 4; r++) {
        int c = c0 + ty + r * 8;
        ts[tx][ty + r * 8] = x[((size_t)b * CC + c) * NN + n0 + tx];
    }
    __syncthreads();
#pragma unroll
    for (int r = 0; r < 4; r++) {
        int n = n0 + ty + r * 8;
        g_xt[((size_t)b * NN + n) * CC + c0 + tx] = __float2bfloat16_rn(ts[ty + r * 8][tx]);
    }
}

// ============================================================
// Kernel 4: q/k projection (bf16 GEMM) -> fp8 outputs.
//   which=0 -> q_t[n][c] e4m3 scaled x32
//   which=1 -> k[c][m] e4m3 AND k_t[m][c] e4m3
// ============================================================
__global__ __launch_bounds__(256, 2) void qk_bf_kernel() {
    extern __shared__ char sdyn[];
    uint32_t sbase = smem_u32(sdyn);
    int b = blockIdx.z >> 1, which = blockIdx.z & 1;
    int o_blk = blockIdx.y * 128, n_blk = blockIdx.x * 128;
    const __nv_bfloat16* A = (which ? g_kwf : g_qwf) + (size_t)b * CC * CC + (size_t)o_blk * CC;
    const __nv_bfloat16* B = g_xt + (size_t)b * NN * CC + (size_t)n_blk * CC;
    const float* bias = (which ? g_kbf : g_qbf) + b * CC;

    float acc[4][4][4] = {};
    bf_gemm(A, CC, B, CC, CC / 64, sdyn, sbase, acc);

    int tid = threadIdx.x, lane = tid & 31, wid = tid >> 5;
    int gid = lane >> 2, tig = lane & 3;
    int wm = (wid & 1) * 64, wn = (wid >> 1) * 32;
    const float qs = which ? 1.0f : QSCALE;

    unsigned char* T = (unsigned char*)sdyn;  // [128 n][144 o-pitch]
#pragma unroll
    for (int mi = 0; mi < 4; mi++) {
        int ol = wm + mi * 16 + gid;
        float bv0 = bias[o_blk + ol], bv1 = bias[o_blk + ol + 8];
#pragma unroll
        for (int ni = 0; ni < 4; ni++) {
            int nl = wn + ni * 8 + tig * 2;
            float v00 = (acc[mi][ni][0] + bv0) * qs;
            float v01 = (acc[mi][ni][1] + bv0) * qs;
            float v10 = (acc[mi][ni][2] + bv1) * qs;
            float v11 = (acc[mi][ni][3] + bv1) * qs;
            unsigned short h0 = pack2e4(v00, v01);
            unsigned short h1 = pack2e4(v10, v11);
            if (which) {
                *(unsigned short*)&g_kv8[((size_t)b * CC + o_blk + ol) * NN + n_blk + nl] = h0;
                *(unsigned short*)&g_kv8[((size_t)b * CC + o_blk + ol + 8) * NN + n_blk + nl] = h1;
            }
            T[nl * 144 + ol] = (unsigned char)(h0 & 0xFF);
            T[(nl + 1) * 144 + ol] = (unsigned char)(h0 >> 8);
            T[nl * 144 + ol + 8] = (unsigned char)(h1 & 0xFF);
            T[(nl + 1) * 144 + ol + 8] = (unsigned char)(h1 >> 8);
        }
    }
    __syncthreads();
    {
        unsigned char* dst = (which ? g_k8t : g_q8) + (size_t)b * NN * CC;
        int row = tid >> 1, hf = tid & 1;
        unsigned char* drow = dst + (size_t)(n_blk + row) * CC + o_blk + hf * 64;
        const unsigned char* srow = T + row * 144 + hf * 64;
#pragma unroll
        for (int j = 0; j < 4; j++)
            ((uint4*)drow)[j] = ((const uint4*)srow)[j];
    }
}

// ============================================================
// Kernel 5: scores (fp8). S'[n][m] = q'_t[n][c] · k_t[m][c]^T  (bf16 out)
// ============================================================
__global__ __launch_bounds__(256, 2) void scores_f8_kernel() {
    extern __shared__ char sdyn[];
    uint32_t sbase = smem_u32(sdyn);
    int b = blockIdx.z;
    int nB = blockIdx.y * 128, mB = blockIdx.x * 128;
    const unsigned char* A = g_q8 + (size_t)b * NN * CC + (size_t)nB * CC;
    const unsigned char* B = g_k8t + (size_t)b * NN * CC + (size_t)mB * CC;

    float acc[4][4][4] = {};
    f8_gemm(A, CC, B, CC, CC / 128, sdyn, sbase, acc);

    int tid = threadIdx.x, lane = tid & 31, wid = tid >> 5;
    int gid = lane >> 2, tig = lane & 3;
    int wm = (wid & 1) * 64, wn = (wid >> 1) * 32;
#pragma unroll
    for (int mi = 0; mi < 4; mi++) {
        int qrow = nB + wm + mi * 16 + gid;
        __nv_bfloat16* p0 = g_s + ((size_t)b * NN + qrow) * NN + mB;
        __nv_bfloat16* p1 = p0 + (size_t)8 * NN;
#pragma unroll
        for (int ni = 0; ni < 4; ni++) {
            int cb = wn + ni * 8 + tig * 2;
            *(unsigned*)(p0 + cb) = packbf(acc[mi][ni][0], acc[mi][ni][1]);
            *(unsigned*)(p1 + cb) = packbf(acc[mi][ni][2], acc[mi][ni][3]);
        }
    }
}

// ============================================================
// Kernel 6: row softmax. Reads bf16 S' (=32*S), writes e4m3 P' (=1024*P).
// ============================================================
__global__ void softmax_kernel() {
    int b = blockIdx.y;
    int row = blockIdx.x;
    const uint4* p = (const uint4*)(g_s + ((size_t)b * NN + row) * NN);
    unsigned char* po = g_p + ((size_t)b * NN + row) * NN;
    int tid = threadIdx.x;

    uint4 u0 = p[tid];
    uint4 u1 = p[tid + 256];
    float vals[16];
    float mx = -1e30f;
    {
        const unsigned us[8] = {u0.x, u0.y, u0.z, u0.w, u1.x, u1.y, u1.z, u1.w};
#pragma unroll
        for (int i = 0; i < 8; i++) {
            __nv_bfloat162 h = *reinterpret_cast<const __nv_bfloat162*>(&us[i]);
            float2 f = __bfloat1622float2(h);
            vals[2 * i] = f.x * QINV;
            vals[2 * i + 1] = f.y * QINV;
            mx = fmaxf(mx, fmaxf(vals[2 * i], vals[2 * i + 1]));
        }
    }
    __shared__ float sred[64];
#pragma unroll
    for (int off = 16; off > 0; off >>= 1)
        mx = fmaxf(mx, __shfl_xor_sync(0xffffffffu, mx, off));
    if ((tid & 31) == 0) sred[tid >> 5] = mx;
    __syncthreads();
    if (tid < 32) {
        float v = (tid < 8) ? sred[tid] : -1e30f;
#pragma unroll
        for (int off = 4; off > 0; off >>= 1)
            v = fmaxf(v, __shfl_xor_sync(0xffffffffu, v, off));
        if (tid == 0) sred[32] = v;
    }
    __syncthreads();
    mx = sred[32];

    float sum = 0.f;
#pragma unroll
    for (int i = 0; i < 16; i++) {
        vals[i] = __expf(vals[i] - mx);
        sum += vals[i];
    }
#pragma unroll
    for (int off = 16; off > 0; off >>= 1)
        sum += __shfl_xor_sync(0xffffffffu, sum, off);
    if ((tid & 31) == 0) sred[tid >> 5] = sum;
    __syncthreads();
    if (tid < 32) {
        float v = (tid < 8) ? sred[tid] : 0.f;
#pragma unroll
        for (int off = 4; off > 0; off >>= 1)
            v += __shfl_xor_sync(0xffffffffu, v, off);
        if (tid == 0) sred[33] = v;
    }
    __syncthreads();
    float inv = PSCALE / sred[33];

    unsigned short h[8];
#pragma unroll
    for (int i = 0; i < 8; i++)
        h[i] = pack2e4(vals[2 * i] * inv, vals[2 * i + 1] * inv);
    uint2 o0, o1;
    o0.x = (unsigned)h[0] | ((unsigned)h[1] << 16);
    o0.y = (unsigned)h[2] | ((unsigned)h[3] << 16);
    o1.x = (unsigned)h[4] | ((unsigned)h[5] << 16);
    o1.y = (unsigned)h[6] | ((unsigned)h[7] << 16);
    *(uint2*)(po + tid * 8) = o0;
    *(uint2*)(po + (tid + 256) * 8) = o1;
}

// ============================================================
// Kernel 7: AV (fp8). D[c][n] = k[c][m] · P'[n][m]^T / 1024 -> att_t[n][c] bf16
// ============================================================
__global__ __launch_bounds__(256, 2) void av_f8_kernel() {
    extern __shared__ char sdyn[];
    uint32_t sbase = smem_u32(sdyn);
    int b = blockIdx.z;
    int cB = blockIdx.y * 128, nB = blockIdx.x * 128;
    const unsigned char* A = g_kv8 + (size_t)b * CC * NN + (size_t)cB * NN;
    const unsigned char* B = g_p + (size_t)b * NN * NN + (size_t)nB * NN;

    float acc[4][4][4] = {};
    f8_gemm(A, NN, B, NN, NN / 128, sdyn, sbase, acc);

    int tid = threadIdx.x, lane = tid & 31, wid = tid >> 5;
    int gid = lane >> 2, tig = lane & 3;
    int wm = (wid & 1) * 64, wn = (wid >> 1) * 32;

    __nv_bfloat16* T = (__nv_bfloat16*)sdyn;  // [128 n][136 c-pitch]
#pragma unroll
    for (int mi = 0; mi < 4; mi++) {
        int cl = wm + mi * 16 + gid;
#pragma unroll
        for (int ni = 0; ni < 4; ni++) {
            int nl = wn + ni * 8 + tig * 2;
            T[nl * 136 + cl] = __float2bfloat16_rn(acc[mi][ni][0] * PINV);
            T[(nl + 1) * 136 + cl] = __float2bfloat16_rn(acc[mi][ni][1] * PINV);
            T[nl * 136 + cl + 8] = __float2bfloat16_rn(acc[mi][ni][2] * PINV);
            T[(nl + 1) * 136 + cl + 8] = __float2bfloat16_rn(acc[mi][ni][3] * PINV);
        }
    }
    __syncthreads();
    {
        int nl = tid >> 1, h = tid & 1;
        __nv_bfloat16* drow = g_attt + ((size_t)b * NN + nB + nl) * CC + cB + h * 64;
        const __nv_bfloat16* srow = T + nl * 136 + h * 64;
#pragma unroll
        for (int j = 0; j < 8; j++)
            *(uint4*)(drow + j * 8) = *(const uint4*)(srow + j * 8);
    }
}

// ============================================================
// Kernel 8: proj + bias + residual (bf16, R6 config).
// ============================================================
__global__ __launch_bounds__(256, 2) void proj_bf_kernel(const float* __restrict__ x,
                                                         const float* __restrict__ pb,
                                                         float* __restrict__ out) {
    extern __shared__ char sdyn[];
    uint32_t sbase = smem_u32(sdyn);
    int b = blockIdx.z;
    int o_blk = blockIdx.y * 128, n_blk = blockIdx.x * 128;
    const __nv_bfloat16* A = g_pwf + (size_t)o_blk * CC;
    const __nv_bfloat16* B = g_attt + (size_t)b * NN * CC + (size_t)n_blk * CC;

    float acc[4][4][4] = {};
    bf_gemm(A, CC, B, CC, CC / 64, sdyn, sbase, acc);

    int tid = threadIdx.x, lane = tid & 31, wid = tid >> 5;
    int gid = lane >> 2, tig = lane & 3;
    int wm = (wid & 1) * 64, wn = (wid >> 1) * 32;
#pragma unroll
    for (int mi = 0; mi < 4; mi++) {
        int o = o_blk + wm + mi * 16 + gid;
        float bv0 = pb[o], bv1 = pb[o + 8];
        size_t base0 = ((size_t)b * CC + o) * NN + n_blk;
        size_t base1 = base0 + (size_t)8 * NN;
#pragma unroll
        for (int ni = 0; ni < 4; ni++) {
            int cb = wn + ni * 8 + tig * 2;
            float2 x0 = *(const float2*)(x + base0 + cb);
            float2 x1 = *(const float2*)(x + base1 + cb);
            *(float2*)(out + base0 + cb) =
                make_float2(acc[mi][ni][0] + bv0 + x0.x, acc[mi][ni][1] + bv0 + x0.y);
            *(float2*)(out + base1 + cb) =
                make_float2(acc[mi][ni][2] + bv1 + x1.x, acc[mi][ni][3] + bv1 + x1.y);
        }
    }
}

// ============================================================
// launch
// ============================================================
extern "C" void kernel_launch(void* const* d_in, const int* in_sizes, int n_in,
                              void* d_out, int out_size) {
    const float* x     = (const float*)d_in[0];
    const float* gamma = (const float*)d_in[1];
    const float* beta  = (const float*)d_in[2];
    const float* q_w   = (const float*)d_in[3];
    const float* q_b   = (const float*)d_in[4];
    const float* k_w   = (const float*)d_in[5];
    const float* k_b   = (const float*)d_in[6];
    const float* p_w   = (const float*)d_in[7];
    const float* p_b   = (const float*)d_in[8];
    float* out = (float*)d_out;

    (void)in_sizes; (void)n_in; (void)out_size;

    cudaFuncSetAttribute(qk_bf_kernel, cudaFuncAttributeMaxDynamicSharedMemorySize, SMEM_DYN);
    cudaFuncSetAttribute(scores_f8_kernel, cudaFuncAttributeMaxDynamicSharedMemorySize, SMEM_DYN);
    cudaFuncSetAttribute(av_f8_kernel, cudaFuncAttributeMaxDynamicSharedMemorySize, SMEM_DYN);
    cudaFuncSetAttribute(proj_bf_kernel, cudaFuncAttributeMaxDynamicSharedMemorySize, SMEM_DYN);

    gn_stats_kernel<<<dim3(BATCH, GG), 256>>>(x);
    fold_kernel<<<dim3(BATCH, 4), 256>>>(q_w, q_b, k_w, k_b, p_w, gamma, beta);
    xt_kernel<<<dim3(NN / 32, CC / 32, BATCH), dim3(32, 8)>>>(x);

    qk_bf_kernel<<<dim3(NN / 128, CC / 128, BATCH * 2), 256, SMEM_DYN>>>();
    scores_f8_kernel<<<dim3(NN / 128, NN / 128, BATCH), 256, SMEM_DYN>>>();
    softmax_kernel<<<dim3(NN, BATCH), 256>>>();
    av_f8_kernel<<<dim3(NN / 128, CC / 128, BATCH), 256, SMEM_DYN>>>();
    proj_bf_kernel<<<dim3(NN / 128, CC / 128, BATCH), 256, SMEM_DYN>>>(x, p_b, out);
}